// round 13
// baseline (speedup 1.0000x reference)
#include <cuda_runtime.h>
#include <cuda_fp16.h>
#include <cuda_bf16.h>
#include <cstdint>

// self_attention_9225589752302 — round 12: split-barrier j-half groups (bar.sync 1/2),
// group-local J/V staging. 3-stage cp.async, reg-cached K, log2 softmax, fp16 GEMM2.
// grid (16 k-tiles, 64 batches), 256 thr, 2 CTAs/SM.

#define NTHREADS 256
#define LOG2E 1.4426950408889634f

// ---- global scratch ----
__device__ __half g_KtHi[4194304];   // [pb][k=1024][c=64], pre-scaled by log2e
__device__ __half g_KtLo[4194304];
__device__ __half g_JHi [4194304];   // [pb][c=64][j=1024]
__device__ __half g_JLo [4194304];
__device__ __half g_VH  [4194304];   // [pb][c=64][j=1024] single fp16

// ---- smem layout: K 16KB | 3 stages x 24KB | LRED ----
#define KHIo 0u
#define KLOo 8192u
#define STG  16384u
#define SSZ  24576u
#define JHIo 0u
#define JLOo 8192u
#define VHo  16384u
#define LRED (16384u + 3u * 24576u)     // 90112
#define SMEM_BYTES (LRED + 1536u)
#define OSTAGE 0u

static __device__ __forceinline__ uint32_t smem_u32(const void* p) {
    uint32_t a;
    asm("{ .reg .u64 t; cvta.to.shared.u64 t, %1; cvt.u32.u64 %0, t; }" : "=r"(a) : "l"(p));
    return a;
}
static __device__ __forceinline__ float ex2f(float x) {
    float r;
    asm("ex2.approx.ftz.f32 %0, %1;" : "=f"(r) : "f"(x));
    return r;
}
static __device__ __forceinline__ void cpa16(uint32_t dst, const void* src) {
    asm volatile("cp.async.cg.shared.global [%0], [%1], 16;" :: "r"(dst), "l"(src));
}
#define CP_COMMIT() asm volatile("cp.async.commit_group;" ::: "memory")
#define CP_WAIT1()  asm volatile("cp.async.wait_group 1;" ::: "memory")
#define CP_WAIT0()  asm volatile("cp.async.wait_group 0;" ::: "memory")
static __device__ __forceinline__ void barg(int id) {
    asm volatile("bar.sync %0, 128;" :: "r"(id) : "memory");
}

static __device__ __forceinline__ void ldsm4(uint32_t r[4], uint32_t a) {
    asm volatile("ldmatrix.sync.aligned.m8n8.x4.shared.b16 {%0,%1,%2,%3}, [%4];"
        : "=r"(r[0]), "=r"(r[1]), "=r"(r[2]), "=r"(r[3]) : "r"(a));
}
static __device__ __forceinline__ void ldsm4t(uint32_t r[4], uint32_t a) {
    asm volatile("ldmatrix.sync.aligned.m8n8.x4.trans.shared.b16 {%0,%1,%2,%3}, [%4];"
        : "=r"(r[0]), "=r"(r[1]), "=r"(r[2]), "=r"(r[3]) : "r"(a));
}
static __device__ __forceinline__ void mma_f16(float d[4], const uint32_t a[4], uint32_t b0, uint32_t b1) {
    asm("mma.sync.aligned.m16n8k16.row.col.f32.f16.f16.f32 "
        "{%0,%1,%2,%3}, {%4,%5,%6,%7}, {%8,%9}, {%0,%1,%2,%3};"
        : "+f"(d[0]), "+f"(d[1]), "+f"(d[2]), "+f"(d[3])
        : "r"(a[0]), "r"(a[1]), "r"(a[2]), "r"(a[3]), "r"(b0), "r"(b1));
}
static __device__ __forceinline__ uint32_t u32h2(__half2 h) { return *(uint32_t*)&h; }

// ---- merged prep ----
__global__ __launch_bounds__(256)
void prep_kernel(const float* __restrict__ K, const float* __restrict__ J,
                 const float* __restrict__ V) {
    __shared__ float s[64][65];
    const int tid = threadIdx.x;
    const unsigned b = blockIdx.x;
    if (b < 2048u) {
        #pragma unroll
        for (int u = 0; u < 2; u++) {
            unsigned f = b * 512u + (unsigned)tid + (unsigned)u * 256u;
            float4 jv = ((const float4*)J)[f];
            float4 vv = ((const float4*)V)[f];
            __half2 h0 = __floats2half2_rn(jv.x, jv.y), h1 = __floats2half2_rn(jv.z, jv.w);
            float2 a0 = __half22float2(h0), a1 = __half22float2(h1);
            __half2 l0 = __floats2half2_rn(jv.x - a0.x, jv.y - a0.y);
            __half2 l1 = __floats2half2_rn(jv.z - a1.x, jv.w - a1.y);
            ((__half2*)g_JHi)[f * 2] = h0; ((__half2*)g_JHi)[f * 2 + 1] = h1;
            ((__half2*)g_JLo)[f * 2] = l0; ((__half2*)g_JLo)[f * 2 + 1] = l1;
            ((__half2*)g_VH)[f * 2]     = __floats2half2_rn(vv.x, vv.y);
            ((__half2*)g_VH)[f * 2 + 1] = __floats2half2_rn(vv.z, vv.w);
        }
    } else {
        const unsigned bb = b - 2048u;
        const unsigned base = (bb >> 4) * 65536u;
        const unsigned k0 = (bb & 15u) * 64u;
        #pragma unroll
        for (int t = 0; t < 16; t++) {
            int flat = tid + t * 256;
            int c = flat >> 6, k = flat & 63;
            s[c][k] = K[base + (unsigned)c * 1024u + k0 + k] * LOG2E;
        }
        __syncthreads();
        #pragma unroll
        for (int t = 0; t < 16; t++) {
            int flat = tid + t * 256;
            int k = flat >> 6, c = flat & 63;
            float x = s[c][k];
            __half h = __float2half_rn(x);
            __half l = __float2half_rn(x - __half2float(h));
            unsigned o = base + (k0 + (unsigned)k) * 64u + (unsigned)c;
            g_KtHi[o] = h;
            g_KtLo[o] = l;
        }
    }
}

// ---- main kernel ----
__global__ __launch_bounds__(NTHREADS, 2)
void attn_mma_kernel(float* __restrict__ Og) {
    extern __shared__ char smem[];
    const uint32_t smb = smem_u32(smem);
    float* lred  = (float*)(smem + LRED);
    float* msm   = lred + 192;
    float* ostage = (float*)(smem + OSTAGE);

    const int tid  = threadIdx.x;
    const int lane = tid & 31;
    const int wid  = tid >> 5;
    const int wm   = wid & 3;
    const int wn   = wid >> 2;          // j-half group (0/1)
    const int gtid = tid & 127;         // thread id within group
    const int m0   = wm * 16;
    const int j0   = wn * 32;
    const unsigned pbo   = (unsigned)blockIdx.y * 65536u;
    const unsigned kbase = (unsigned)blockIdx.x * 64u;

    // group-local copy addressing: per buffer 256 chunks / 128 threads = 2 each
    // chunk: c = flat>>2, ch = flat&3 ; jbyte = wn*64 + ch*16
    uint32_t dstoff[2];
    unsigned srcoff[2];
    #pragma unroll
    for (int t = 0; t < 2; t++) {
        int flat = gtid + t * 128;
        uint32_t c = (uint32_t)(flat >> 2), ch = (uint32_t)(flat & 3);
        uint32_t jb = (uint32_t)(wn * 64) + ch * 16u;
        dstoff[t] = c * 128u + (jb ^ ((c & 7u) << 4));
        srcoff[t] = pbo + c * 1024u + (unsigned)(wn * 32) + ch * 8u;
    }

    // ---------- prologue: K tile (all threads) + stages 0,1 (group halves) ----------
    #pragma unroll
    for (int t = 0; t < 2; t++) {
        int flat = tid + t * NTHREADS;
        uint32_t k = (uint32_t)(flat >> 3), ch = (uint32_t)(flat & 7);
        uint32_t dst = k * 128u + ((ch * 16u) ^ ((k & 7u) << 4));
        unsigned so = pbo + (kbase + k) * 64u + ch * 8u;
        cpa16(smb + KHIo + dst, g_KtHi + so);
        cpa16(smb + KLOo + dst, g_KtLo + so);
    }
    #pragma unroll
    for (int t = 0; t < 2; t++) {
        cpa16(smb + STG + JHIo + dstoff[t], g_JHi + srcoff[t]);
        cpa16(smb + STG + JLOo + dstoff[t], g_JLo + srcoff[t]);
        cpa16(smb + STG + VHo  + dstoff[t], g_VH  + srcoff[t]);
    }
    CP_COMMIT();
    #pragma unroll
    for (int t = 0; t < 2; t++) {
        cpa16(smb + STG + SSZ + JHIo + dstoff[t], g_JHi + srcoff[t] + 64u);
        cpa16(smb + STG + SSZ + JLOo + dstoff[t], g_JLo + srcoff[t] + 64u);
        cpa16(smb + STG + SSZ + VHo  + dstoff[t], g_VH  + srcoff[t] + 64u);
    }
    CP_COMMIT();
    CP_WAIT1();   // K + stage0
    __syncthreads();

    // lane-constant address pieces
    const uint32_t xorl  = (uint32_t)(lane & 7) << 4;
    const uint32_t aRow0 = (uint32_t)(m0 + (lane & 15)) * 128u;
    const uint32_t aColH = (uint32_t)((lane >> 4) << 4);
    const uint32_t bRowJ = (uint32_t)((lane & 15)) * 128u;
    const uint32_t bColJ = (uint32_t)((lane >> 4) << 4);
    const uint32_t vRow  = (uint32_t)(lane & 7) * 128u;
    const uint32_t vColH = (uint32_t)((lane >> 3) << 4);
    const uint32_t vcol  = ((uint32_t)(j0 * 2) + vColH) ^ xorl;

    // ---------- cache K fragments in registers ----------
    uint32_t kfh[4][4], kfl[4][4];
    #pragma unroll
    for (int ks = 0; ks < 4; ks++) {
        uint32_t acol = ((uint32_t)(ks * 32) + aColH) ^ xorl;
        ldsm4(kfh[ks], smb + KHIo + aRow0 + acol);
        ldsm4(kfl[ks], smb + KLOo + aRow0 + acol);
    }

    float D2[8][4];
    #pragma unroll
    for (int nt = 0; nt < 8; nt++)
        #pragma unroll
        for (int i = 0; i < 4; i++) D2[nt][i] = 0.0f;
    float rsum[2] = {0.0f, 0.0f};
    float mrow0 = -1e30f, mrow1 = -1e30f;

    uint32_t curst = 0;
    const int mybar = 1 + wn;

    for (int jt = 0; jt < 16; jt++) {
        const uint32_t cur = STG + curst * SSZ;

        // issue copies for jt+2 into stage (curst+2)%3 (own j-half only)
        if (jt < 14) {
            uint32_t ns = curst + 2u; if (ns >= 3u) ns -= 3u;
            const uint32_t nxt = STG + ns * SSZ;
            unsigned go = (unsigned)(jt + 2) * 64u;
            #pragma unroll
            for (int t = 0; t < 2; t++) {
                cpa16(smb + nxt + JHIo + dstoff[t], g_JHi + srcoff[t] + go);
                cpa16(smb + nxt + JLOo + dstoff[t], g_JLo + srcoff[t] + go);
                cpa16(smb + nxt + VHo  + dstoff[t], g_VH  + srcoff[t] + go);
            }
            CP_COMMIT();
        }

        // ---------- GEMM1: S̃[16 x 32] (log2 domain) fp16 3-pass ----------
        float S[4][4];
        #pragma unroll
        for (int nt = 0; nt < 4; nt++)
            #pragma unroll
            for (int i = 0; i < 4; i++) S[nt][i] = 0.0f;

        #pragma unroll
        for (int ks = 0; ks < 4; ks++) {
            uint32_t jrow = (uint32_t)(ks * 16) * 128u + bRowJ;
            #pragma unroll
            for (int ntp = 0; ntp < 2; ntp++) {
                uint32_t bh[4], bl[4];
                uint32_t bcol = ((uint32_t)((j0 + ntp * 16) * 2) + bColJ) ^ xorl;
                ldsm4t(bh, smb + cur + JHIo + jrow + bcol);
                ldsm4t(bl, smb + cur + JLOo + jrow + bcol);
                #pragma unroll
                for (int q = 0; q < 2; q++) {
                    int nt = 2 * ntp + q;
                    mma_f16(S[nt], kfh[ks], bh[2 * q], bh[2 * q + 1]);
                    mma_f16(S[nt], kfh[ks], bl[2 * q], bl[2 * q + 1]);
                    mma_f16(S[nt], kfl[ks], bh[2 * q], bh[2 * q + 1]);
                }
            }
        }

        // ---------- online softmax (log2 domain) ----------
        float mx0 = -1e30f, mx1 = -1e30f;
        #pragma unroll
        for (int nt = 0; nt < 4; nt++) {
            mx0 = fmaxf(mx0, fmaxf(S[nt][0], S[nt][1]));
            mx1 = fmaxf(mx1, fmaxf(S[nt][2], S[nt][3]));
        }
        mx0 = fmaxf(mx0, __shfl_xor_sync(0xffffffffu, mx0, 1));
        mx0 = fmaxf(mx0, __shfl_xor_sync(0xffffffffu, mx0, 2));
        mx1 = fmaxf(mx1, __shfl_xor_sync(0xffffffffu, mx1, 1));
        mx1 = fmaxf(mx1, __shfl_xor_sync(0xffffffffu, mx1, 2));
        bool changed = (mx0 > mrow0) || (mx1 > mrow1);
        if (__any_sync(0xffffffffu, changed)) {
            float nm0 = fmaxf(mrow0, mx0), nm1 = fmaxf(mrow1, mx1);
            float a0 = ex2f(mrow0 - nm0), a1 = ex2f(mrow1 - nm1);
            mrow0 = nm0; mrow1 = nm1;
            rsum[0] *= a0; rsum[1] *= a1;
            #pragma unroll
            for (int nt = 0; nt < 8; nt++) {
                D2[nt][0] *= a0; D2[nt][1] *= a0;
                D2[nt][2] *= a1; D2[nt][3] *= a1;
            }
        }

        uint32_t phi[2][4];
        #pragma unroll
        for (int g = 0; g < 2; g++)
            #pragma unroll
            for (int q = 0; q < 2; q++) {
                const float* s = S[2 * g + q];
                float p0 = ex2f(s[0] - mrow0), p1 = ex2f(s[1] - mrow0);
                float p2 = ex2f(s[2] - mrow1), p3 = ex2f(s[3] - mrow1);
                rsum[0] += p0 + p1;
                rsum[1] += p2 + p3;
                phi[g][2 * q]     = u32h2(__floats2half2_rn(p0, p1));
                phi[g][2 * q + 1] = u32h2(__floats2half2_rn(p2, p3));
            }

        // ---------- GEMM2: D2 += P x V^T, fp16 1-pass ----------
        #pragma unroll
        for (int nt = 0; nt < 8; nt++) {
            uint32_t vh[4];
            uint32_t vr = (uint32_t)(nt * 8) * 128u + vRow;
            ldsm4(vh, smb + cur + VHo + vr + vcol);
            #pragma unroll
            for (int g = 0; g < 2; g++)
                mma_f16(D2[nt], phi[g], vh[2 * g], vh[2 * g + 1]);
        }

        if (jt < 14) { CP_WAIT1(); }
        else if (jt == 14) { CP_WAIT0(); }
        barg(mybar);   // group-local barrier: own j-half stages only
        curst = (curst == 2u) ? 0u : curst + 1u;
    }

    // ---------- Epilogue (full-CTA syncs) ----------
    const int r = m0 + (lane >> 2);
    if ((lane & 3) == 0) {
        msm[wn * 64 + r]     = mrow0;
        msm[wn * 64 + r + 8] = mrow1;
    }
    __syncthreads();
    {
        float M0 = fmaxf(msm[r], msm[64 + r]);
        float M1 = fmaxf(msm[r + 8], msm[64 + r + 8]);
        float s0 = ex2f(mrow0 - M0), s1 = ex2f(mrow1 - M1);
        rsum[0] *= s0; rsum[1] *= s1;
        #pragma unroll
        for (int nt = 0; nt < 8; nt++) {
            D2[nt][0] *= s0; D2[nt][1] *= s0;
            D2[nt][2] *= s1; D2[nt][3] *= s1;
        }
    }

    #pragma unroll
    for (int rr = 0; rr < 2; rr++) {
        float v = rsum[rr];
        v += __shfl_xor_sync(0xffffffffu, v, 1);
        v += __shfl_xor_sync(0xffffffffu, v, 2);
        if ((lane & 3) == 0)
            lred[wn * 64 + m0 + rr * 8 + (lane >> 2)] = v;
    }
    __syncthreads();
    if (tid < 64) lred[128 + tid] = 1.0f / (lred[tid] + lred[64 + tid]);

    if (wn == 0) {
        #pragma unroll
        for (int nt = 0; nt < 8; nt++) {
            int c0 = nt * 8 + 2 * (lane & 3);
            int rw = m0 + (lane >> 2);
            ostage[c0 * 64 + rw]           = D2[nt][0];
            ostage[(c0 + 1) * 64 + rw]     = D2[nt][1];
            ostage[c0 * 64 + rw + 8]       = D2[nt][2];
            ostage[(c0 + 1) * 64 + rw + 8] = D2[nt][3];
        }
    }
    __syncthreads();
    if (wn == 1) {
        #pragma unroll
        for (int nt = 0; nt < 8; nt++) {
            int c0 = nt * 8 + 2 * (lane & 3);
            int rw = m0 + (lane >> 2);
            ostage[c0 * 64 + rw]           += D2[nt][0];
            ostage[(c0 + 1) * 64 + rw]     += D2[nt][1];
            ostage[c0 * 64 + rw + 8]       += D2[nt][2];
            ostage[(c0 + 1) * 64 + rw + 8] += D2[nt][3];
        }
    }
    __syncthreads();

    #pragma unroll
    for (int t = 0; t < 4; t++) {
        int flat = tid + t * NTHREADS;
        int c = flat >> 4, k4 = flat & 15;
        float4 v  = *(float4*)(ostage + c * 64 + k4 * 4);
        float4 iv = *(float4*)(lred + 128 + k4 * 4);
        v.x *= iv.x; v.y *= iv.y; v.z *= iv.z; v.w *= iv.w;
        *(float4*)(Og + pbo + (unsigned)c * 1024u + kbase + (unsigned)k4 * 4u) = v;
    }
}

extern "C" void kernel_launch(void* const* d_in, const int* in_sizes, int n_in,
                              void* d_out, int out_size) {
    const float* Kg = (const float*)d_in[0];
    const float* Jg = (const float*)d_in[1];
    const float* Vg = (const float*)d_in[2];
    float* Og = (float*)d_out;

    prep_kernel<<<3072, 256>>>(Kg, Jg, Vg);

    cudaFuncSetAttribute(attn_mma_kernel,
                         cudaFuncAttributeMaxDynamicSharedMemorySize, SMEM_BYTES);
    dim3 grid(16, 64);
    attn_mma_kernel<<<grid, NTHREADS, SMEM_BYTES>>>(Og);
}